// round 7
// baseline (speedup 1.0000x reference)
#include <cuda_runtime.h>
#include <math.h>

// Problem constants (fixed shapes)
#define TT    2048
#define HH    16
#define NOPE  128
#define ROPE  64
#define DQK   192      // NOPE + ROPE
#define LORA  512
#define VDIM  128
#define OUTD  (HH * VDIM)          // 2048
#define KVCOLS (HH * 256)          // 4096: per head [128 k_nope | 128 v]
#define SCALE 0.07216878364870323f // 1/sqrt(192)

// Scratch: per-head K_nope (128) and folded V (128), interleaved per head.
// g_kv[t*4096 + h*256 + 0..127]   = k_nope[t,h,:]
// g_kv[t*4096 + h*256 + 128..255] = V_h[t,:] = sum_l kc[t,l]*w_uv[h,l,:]
__device__ float g_kv[TT * KVCOLS];

// ---------------------------------------------------------------------------
// Kernel 1: fused precompute GEMM  C[2048 x 4096] = kc[2048x512] @ B
//   B column c: h=c>>8, d=c&255
//     d < 128  -> w_kv_b[:, h*256 + d]          (k_nope projection)
//     d >= 128 -> w_uv[h, :, d-128]             (folded V projection)
// 128x128 tiles, K-tile 32, 256 threads, 8x8 micro-tile, float4 smem reads,
// register-staged double buffering (next tile's LDGs overlap the compute).
// ---------------------------------------------------------------------------
#define GBM 128
#define GBN 128
#define GBK 32
#define AS_STRIDE 132   // 128+4 (16B aligned, shifts k-rows across banks)

__global__ void __launch_bounds__(256) kv_gemm_kernel(
    const float* __restrict__ kc,
    const float* __restrict__ w_kv_b,
    const float* __restrict__ w_uv)
{
    __shared__ float As[GBK][AS_STRIDE];   // [k][m]
    __shared__ float Bs[GBK][GBN];         // [k][n]

    const int m0 = blockIdx.y * GBM;
    const int n0 = blockIdx.x * GBN;
    const int tid = threadIdx.x;
    const int tx = tid & 15;
    const int ty = tid >> 4;

    const int h    = n0 >> 8;
    const bool is_v = (n0 & 128) != 0;

    // A load mapping: warp covers 4 rows x full 32-k (coalesced 128B rows)
    const int a_row = tid >> 3;           // 0..31 (+32 per q)
    const int a_k4  = (tid & 7) * 4;      // 0,4,...,28
    // B load mapping: warp covers one full k-row of 128 n (coalesced 512B)
    const int b_k   = tid >> 5;           // 0..7 (+8 per q)
    const int b_n4  = (tid & 31) * 4;     // 0,4,...,124

    float acc[8][8];
    #pragma unroll
    for (int i = 0; i < 8; i++)
        #pragma unroll
        for (int j = 0; j < 8; j++) acc[i][j] = 0.0f;

    float4 a_stg[4], b_stg[4];

    // Prologue: fetch tile 0 into registers
    #pragma unroll
    for (int q = 0; q < 4; q++) {
        a_stg[q] = *(const float4*)&kc[(m0 + a_row + q * 32) * LORA + a_k4];
        int kg = b_k + q * 8;
        if (!is_v) b_stg[q] = *(const float4*)&w_kv_b[kg * KVCOLS + n0 + b_n4];
        else       b_stg[q] = *(const float4*)&w_uv[(h * LORA + kg) * VDIM + (b_n4 + (n0 & 127))];
    }

    for (int k0 = 0; k0 < LORA; k0 += GBK) {
        // Commit staged tile to smem
        #pragma unroll
        for (int q = 0; q < 4; q++) {
            int r = a_row + q * 32;
            As[a_k4 + 0][r] = a_stg[q].x;
            As[a_k4 + 1][r] = a_stg[q].y;
            As[a_k4 + 2][r] = a_stg[q].z;
            As[a_k4 + 3][r] = a_stg[q].w;
            *(float4*)&Bs[b_k + q * 8][b_n4] = b_stg[q];
        }
        __syncthreads();

        // Issue next tile's LDGs early (latency hidden under compute below)
        const int kn = k0 + GBK;
        if (kn < LORA) {
            #pragma unroll
            for (int q = 0; q < 4; q++) {
                a_stg[q] = *(const float4*)&kc[(m0 + a_row + q * 32) * LORA + kn + a_k4];
                int kg = kn + b_k + q * 8;
                if (!is_v) b_stg[q] = *(const float4*)&w_kv_b[kg * KVCOLS + n0 + b_n4];
                else       b_stg[q] = *(const float4*)&w_uv[(h * LORA + kg) * VDIM + (b_n4 + (n0 & 127))];
            }
        }

        #pragma unroll
        for (int k = 0; k < GBK; k++) {
            float4 a0 = *(const float4*)&As[k][ty * 4];
            float4 a1 = *(const float4*)&As[k][64 + ty * 4];
            float4 b0 = *(const float4*)&Bs[k][tx * 4];
            float4 b1 = *(const float4*)&Bs[k][64 + tx * 4];
            float a[8] = {a0.x, a0.y, a0.z, a0.w, a1.x, a1.y, a1.z, a1.w};
            float b[8] = {b0.x, b0.y, b0.z, b0.w, b1.x, b1.y, b1.z, b1.w};
            #pragma unroll
            for (int i = 0; i < 8; i++)
                #pragma unroll
                for (int j = 0; j < 8; j++)
                    acc[i][j] = fmaf(a[i], b[j], acc[i][j]);
        }
        __syncthreads();
    }

    // Epilogue: rows {ty*4+i, 64+ty*4+i}, cols {tx*4.., 64+tx*4..} as float4
    #pragma unroll
    for (int ig = 0; ig < 2; ig++) {
        #pragma unroll
        for (int i = 0; i < 4; i++) {
            int r = m0 + ig * 64 + ty * 4 + i;
            #pragma unroll
            for (int jg = 0; jg < 2; jg++) {
                float4 v;
                v.x = acc[ig * 4 + i][jg * 4 + 0];
                v.y = acc[ig * 4 + i][jg * 4 + 1];
                v.z = acc[ig * 4 + i][jg * 4 + 2];
                v.w = acc[ig * 4 + i][jg * 4 + 3];
                *(float4*)&g_kv[r * KVCOLS + n0 + jg * 64 + tx * 4] = v;
            }
        }
    }
}

// ---------------------------------------------------------------------------
// Kernel 2: causal flash attention per (q-tile of 64, head).
//  Q: (T,H,192)   K_h: [k_nope(128) | k_pe(64)]   V_h: 128
//  S-tile 64x64, 256 threads (16x16).
//  STRIDED micro-tile mapping (bank-conflict-free LDS.128):
//    thread (tx,ty) owns S rows {ty+16i}, S cols {tx+16j}  (i,j = 0..3)
//    and O cols {tx*4..tx*4+3} and {64+tx*4..64+tx*4+3}.
//  Pipelined loads: tile t+1's K/V LDGs issue into registers right after the
//  post-softmax sync, land under the PV FMA block, and are committed to smem
//  (K single-buffered — dead after QK; V double-buffered) before the tile-end
//  barrier, which drains the STSs. 1 CTA/SM (smem 183 KB) -> registers free.
//  LPT scheduling: blockIdx.x = 0 maps to the LONGEST q-tile.
// ---------------------------------------------------------------------------
#define QK_STRIDE 196   // 192+4: lane offset tx*196 mod 32 = 4*tx -> conflict-free
#define P_STRIDE  68

__global__ void __launch_bounds__(256, 1) mla_attn_kernel(
    const float* __restrict__ query,
    const float* __restrict__ kpe,
    float* __restrict__ out)
{
    extern __shared__ float sm[];
    float* Qs = sm;                          // 64*196
    float* Ks = Qs + 64 * QK_STRIDE;         // 64*196
    float* Vs = Ks + 64 * QK_STRIDE;         // 2 * 64*128 (double buffer)
    float* Ps = Vs + 2 * 64 * VDIM;          // 64*68

    const int m0 = (gridDim.x - 1 - blockIdx.x) * 64;   // longest-first
    const int h  = blockIdx.y;
    const int tid = threadIdx.x;
    const int tx = tid & 15;
    const int ty = tid >> 4;

    // Per-thread load slices (fixed across tiles):
    //  K: 12 float4 -> rows kr_q = (tid + q*256)/12? Use contiguous mapping:
    //     i = tid + q*256, q = 0..11 over 64*48 float4s
    //  V: 8 float4 over 64*32 float4s
    // Load Q tile (64 x 192)
    #pragma unroll
    for (int q = 0; q < 12; q++) {
        int i  = tid + q * 256;           // 0..3071
        int r  = i / 48;
        int c4 = (i % 48) * 4;
        *(float4*)&Qs[r * QK_STRIDE + c4] =
            *(const float4*)&query[((m0 + r) * HH + h) * DQK + c4];
    }

    float o[4][8];
    #pragma unroll
    for (int i = 0; i < 4; i++)
        #pragma unroll
        for (int j = 0; j < 8; j++) o[i][j] = 0.0f;
    float mrow[4], lrow[4];
    #pragma unroll
    for (int i = 0; i < 4; i++) { mrow[i] = -INFINITY; lrow[i] = 0.0f; }

    // Prologue: load K(0), V(0) directly to smem (buffer 0)
    #pragma unroll
    for (int q = 0; q < 12; q++) {
        int i  = tid + q * 256;
        int s  = i / 48;
        int c4 = (i % 48) * 4;
        float4 v;
        if (c4 < NOPE) v = *(const float4*)&g_kv[s * KVCOLS + h * 256 + c4];
        else           v = *(const float4*)&kpe[s * ROPE + (c4 - NOPE)];
        *(float4*)&Ks[s * QK_STRIDE + c4] = v;
    }
    #pragma unroll
    for (int q = 0; q < 8; q++) {
        int i  = tid + q * 256;
        int s  = i / 32;
        int c4 = (i % 32) * 4;
        *(float4*)&Vs[s * VDIM + c4] =
            *(const float4*)&g_kv[s * KVCOLS + h * 256 + 128 + c4];
    }
    __syncthreads();

    const int ntiles = m0 / 64 + 1;
    for (int t = 0; t < ntiles; t++) {
        const int n0  = t * 64;
        const int cur = t & 1;
        float* Vcur = Vs + cur * 64 * VDIM;

        // S = Q K^T : acc[i][j] = S[ty+16i][tx+16j]
        float acc[4][4];
        #pragma unroll
        for (int i = 0; i < 4; i++)
            #pragma unroll
            for (int j = 0; j < 4; j++) acc[i][j] = 0.0f;

        #pragma unroll 4
        for (int k4 = 0; k4 < DQK; k4 += 4) {
            float4 q[4], kk[4];
            #pragma unroll
            for (int i = 0; i < 4; i++)
                q[i] = *(const float4*)&Qs[(ty + 16 * i) * QK_STRIDE + k4];
            #pragma unroll
            for (int j = 0; j < 4; j++)
                kk[j] = *(const float4*)&Ks[(tx + 16 * j) * QK_STRIDE + k4];
            #pragma unroll
            for (int i = 0; i < 4; i++)
                #pragma unroll
                for (int j = 0; j < 4; j++) {
                    acc[i][j] = fmaf(q[i].x, kk[j].x, acc[i][j]);
                    acc[i][j] = fmaf(q[i].y, kk[j].y, acc[i][j]);
                    acc[i][j] = fmaf(q[i].z, kk[j].z, acc[i][j]);
                    acc[i][j] = fmaf(q[i].w, kk[j].w, acc[i][j]);
                }
        }

        // mask + scale + online softmax (row reduce over 16 tx lanes)
        #pragma unroll
        for (int i = 0; i < 4; i++) {
            const int mg = m0 + ty + 16 * i;
            float rmax = -INFINITY;
            #pragma unroll
            for (int j = 0; j < 4; j++) {
                int ng = n0 + tx + 16 * j;
                float sv = (ng <= mg) ? acc[i][j] * SCALE : -INFINITY;
                acc[i][j] = sv;
                rmax = fmaxf(rmax, sv);
            }
            #pragma unroll
            for (int off = 8; off; off >>= 1)
                rmax = fmaxf(rmax, __shfl_xor_sync(0xffffffffu, rmax, off));
            float mnew = fmaxf(mrow[i], rmax);           // finite (col n0 <= mg)
            float corr = __expf(mrow[i] - mnew);
            float rsum = 0.0f;
            #pragma unroll
            for (int j = 0; j < 4; j++) {
                float p = __expf(acc[i][j] - mnew);      // masked -> exp(-inf)=0
                Ps[(ty + 16 * i) * P_STRIDE + tx + 16 * j] = p;
                rsum += p;
            }
            #pragma unroll
            for (int off = 8; off; off >>= 1)
                rsum += __shfl_xor_sync(0xffffffffu, rsum, off);
            lrow[i] = lrow[i] * corr + rsum;
            mrow[i] = mnew;
            #pragma unroll
            for (int j = 0; j < 8; j++) o[i][j] *= corr;
        }
        __syncthreads();   // (C) Ps visible; Ks reads (QK) done -> Ks writable

        // Prefetch tile t+1 K/V into registers (lands under PV below)
        const bool more = (t + 1 < ntiles);
        float4 kstg[12], vstg[8];
        if (more) {
            const int nn = (t + 1) * 64;
            #pragma unroll
            for (int q = 0; q < 12; q++) {
                int i  = tid + q * 256;
                int s  = i / 48;
                int c4 = (i % 48) * 4;
                if (c4 < NOPE)
                    kstg[q] = *(const float4*)&g_kv[(nn + s) * KVCOLS + h * 256 + c4];
                else
                    kstg[q] = *(const float4*)&kpe[(nn + s) * ROPE + (c4 - NOPE)];
            }
            #pragma unroll
            for (int q = 0; q < 8; q++) {
                int i  = tid + q * 256;
                int s  = i / 32;
                int c4 = (i % 32) * 4;
                vstg[q] = *(const float4*)&g_kv[(nn + s) * KVCOLS + h * 256 + 128 + c4];
            }
        }

        // O += P V : o[i][c]   <-> col tx*4+c        (c = 0..3)
        //            o[i][4+c] <-> col 64 + tx*4 + c
        #pragma unroll 8
        for (int s = 0; s < 64; s++) {
            float p0 = Ps[(ty +  0) * P_STRIDE + s];
            float p1 = Ps[(ty + 16) * P_STRIDE + s];
            float p2 = Ps[(ty + 32) * P_STRIDE + s];
            float p3 = Ps[(ty + 48) * P_STRIDE + s];
            float4 va = *(const float4*)&Vcur[s * VDIM + tx * 4];
            float4 vb = *(const float4*)&Vcur[s * VDIM + 64 + tx * 4];
            o[0][0] = fmaf(p0, va.x, o[0][0]); o[0][1] = fmaf(p0, va.y, o[0][1]);
            o[0][2] = fmaf(p0, va.z, o[0][2]); o[0][3] = fmaf(p0, va.w, o[0][3]);
            o[0][4] = fmaf(p0, vb.x, o[0][4]); o[0][5] = fmaf(p0, vb.y, o[0][5]);
            o[0][6] = fmaf(p0, vb.z, o[0][6]); o[0][7] = fmaf(p0, vb.w, o[0][7]);
            o[1][0] = fmaf(p1, va.x, o[1][0]); o[1][1] = fmaf(p1, va.y, o[1][1]);
            o[1][2] = fmaf(p1, va.z, o[1][2]); o[1][3] = fmaf(p1, va.w, o[1][3]);
            o[1][4] = fmaf(p1, vb.x, o[1][4]); o[1][5] = fmaf(p1, vb.y, o[1][5]);
            o[1][6] = fmaf(p1, vb.z, o[1][6]); o[1][7] = fmaf(p1, vb.w, o[1][7]);
            o[2][0] = fmaf(p2, va.x, o[2][0]); o[2][1] = fmaf(p2, va.y, o[2][1]);
            o[2][2] = fmaf(p2, va.z, o[2][2]); o[2][3] = fmaf(p2, va.w, o[2][3]);
            o[2][4] = fmaf(p2, vb.x, o[2][4]); o[2][5] = fmaf(p2, vb.y, o[2][5]);
            o[2][6] = fmaf(p2, vb.z, o[2][6]); o[2][7] = fmaf(p2, vb.w, o[2][7]);
            o[3][0] = fmaf(p3, va.x, o[3][0]); o[3][1] = fmaf(p3, va.y, o[3][1]);
            o[3][2] = fmaf(p3, va.z, o[3][2]); o[3][3] = fmaf(p3, va.w, o[3][3]);
            o[3][4] = fmaf(p3, vb.x, o[3][4]); o[3][5] = fmaf(p3, vb.y, o[3][5]);
            o[3][6] = fmaf(p3, vb.z, o[3][6]); o[3][7] = fmaf(p3, vb.w, o[3][7]);
        }

        // Commit staged tile t+1 to smem (K in-place; V into the other buffer)
        if (more) {
            float* Vnxt = Vs + (cur ^ 1) * 64 * VDIM;
            #pragma unroll
            for (int q = 0; q < 12; q++) {
                int i  = tid + q * 256;
                int s  = i / 48;
                int c4 = (i % 48) * 4;
                *(float4*)&Ks[s * QK_STRIDE + c4] = kstg[q];
            }
            #pragma unroll
            for (int q = 0; q < 8; q++) {
                int i  = tid + q * 256;
                int s  = i / 32;
                int c4 = (i % 32) * 4;
                *(float4*)&Vnxt[s * VDIM + c4] = vstg[q];
            }
        }
        __syncthreads();   // (D) STS drained before next QK; Ps reads done
    }

    // Epilogue: normalize and store. out shape (T, H*VDIM)
    #pragma unroll
    for (int i = 0; i < 4; i++) {
        float inv_l = 1.0f / lrow[i];
        const int row = m0 + ty + 16 * i;
        #pragma unroll
        for (int jj = 0; jj < 2; jj++)
            #pragma unroll
            for (int c = 0; c < 4; c++)
                out[row * OUTD + h * VDIM + jj * 64 + tx * 4 + c] =
                    o[i][jj * 4 + c] * inv_l;
    }
}

// ---------------------------------------------------------------------------
// Launch
// ---------------------------------------------------------------------------
extern "C" void kernel_launch(void* const* d_in, const int* in_sizes, int n_in,
                              void* d_out, int out_size)
{
    const float* query  = (const float*)d_in[0];
    const float* kc     = (const float*)d_in[1];
    const float* kpe    = (const float*)d_in[2];
    const float* w_kv_b = (const float*)d_in[3];
    const float* w_uv   = (const float*)d_in[4];
    float* out = (float*)d_out;

    const int attn_smem = (64 * QK_STRIDE * 2 + 2 * 64 * VDIM + 64 * P_STRIDE) * (int)sizeof(float);
    cudaFuncSetAttribute(mla_attn_kernel,
                         cudaFuncAttributeMaxDynamicSharedMemorySize, attn_smem);

    kv_gemm_kernel<<<dim3(KVCOLS / GBN, TT / GBM), 256>>>(kc, w_kv_b, w_uv);
    mla_attn_kernel<<<dim3(TT / 64, HH), 256, attn_smem>>>(query, kpe, out);
}